// round 12
// baseline (speedup 1.0000x reference)
#include <cuda_runtime.h>
#include <cuda_bf16.h>
#include <cstdint>
#include <cstddef>

#define DEV_INLINE __device__ __forceinline__

// ---------------- problem constants (fixed shapes) ----------------
constexpr int N_ROWS = 4096;
constexpr int DIM    = 512;
constexpr int NCLS   = 50000;
constexpr float S_SCALE    = 30.0f;
constexpr float MARGIN_COS = 0.9210609940028851f;  // cos(0.4)
constexpr float MARGIN_SIN = 0.3894183423086505f;  // sin(0.4)

// ---------------- GEMM tiling ----------------
constexpr int BM = 128;
constexpr int BN = 128;
constexpr int BK = 64;                 // 64 bf16 = 128B rows (SW128 atom)
constexpr int NKI = DIM / BK;          // 8 k-iterations
constexpr int NSTAGE = 3;
constexpr int NTHREADS = 128;          // 4 warps, 2x2 grid, 64x64 warp tiles
constexpr int MTILES = N_ROWS / BM;                  // 32
constexpr int NTILES = (NCLS + BN - 1) / BN;         // 391 (last masked)

constexpr uint32_t A_STAGE = BM * 128;               // 16384
constexpr uint32_t B_STAGE = BN * 128;               // 16384
constexpr uint32_t STAGE_BYTES = A_STAGE + B_STAGE;  // 32768
constexpr uint32_t SMEM_EXCL = NSTAGE * STAGE_BYTES;         // 98304
constexpr uint32_t SMEM_TG   = SMEM_EXCL + BM * 4;           // 98816
constexpr uint32_t SMEM_MBAR = SMEM_TG + BM * 4;             // 99328
constexpr uint32_t SMEM_TOTAL = SMEM_MBAR + NSTAGE * 16;     // 99376 (x2 CTA ~199KB)

// mbar layout: full[s] at SMEM_MBAR + s*16, empty[s] at +8
#define FULL_MB(s)  (sb + SMEM_MBAR + (s) * 16)
#define EMPTY_MB(s) (sb + SMEM_MBAR + (s) * 16 + 8)

// ---------------- device scratch (allocation-free rule) ----------------
__device__ __nv_bfloat16 g_xbf[(size_t)N_ROWS * DIM];   // normalized x, bf16
__device__ __nv_bfloat16 g_wbf[(size_t)NCLS * DIM];     // W, bf16 (51MB, mostly L2)
__device__ float g_excl[N_ROWS];
__device__ float g_tgt[N_ROWS];
__device__ float g_sum;

// ---------------- helpers ----------------
DEV_INLINE uint32_t smem_u32(const void* p) { return (uint32_t)__cvta_generic_to_shared(p); }
DEV_INLINE uint32_t swz(uint32_t o) { return o ^ ((o >> 3) & 0x70); }

DEV_INLINE void cp16(uint32_t dst, const void* src) {
    asm volatile("cp.async.cg.shared.global [%0], [%1], 16;" :: "r"(dst), "l"(src));
}

DEV_INLINE void cp_arrive(uint32_t mbar) {
    asm volatile("cp.async.mbarrier.arrive.noinc.shared.b64 [%0];"
                 :: "r"(mbar) : "memory");
}

DEV_INLINE void mbar_arrive(uint32_t mbar) {
    asm volatile("mbarrier.arrive.shared.b64 _, [%0];" :: "r"(mbar) : "memory");
}

DEV_INLINE void mbar_wait(uint32_t mbar, uint32_t parity) {
    asm volatile(
        "{\n\t.reg .pred P1;\n\t"
        "WL_%=:\n\t"
        "mbarrier.try_wait.parity.acquire.cta.shared::cta.b64 P1, [%0], %1, 0x989680;\n\t"
        "@P1 bra.uni WD_%=;\n\t"
        "bra.uni WL_%=;\n\t"
        "WD_%=:\n\t}"
        :: "r"(mbar), "r"(parity) : "memory");
}

DEV_INLINE void ldm_x4(uint32_t& r0, uint32_t& r1, uint32_t& r2, uint32_t& r3,
                       uint32_t addr) {
    asm volatile("ldmatrix.sync.aligned.m8n8.x4.shared.b16 {%0,%1,%2,%3}, [%4];"
                 : "=r"(r0), "=r"(r1), "=r"(r2), "=r"(r3) : "r"(addr));
}

DEV_INLINE void mma_bf16(float* d, const uint32_t* a, uint32_t b0, uint32_t b1) {
    asm volatile(
        "mma.sync.aligned.m16n8k16.row.col.f32.bf16.bf16.f32 "
        "{%0,%1,%2,%3}, {%4,%5,%6,%7}, {%8,%9}, {%0,%1,%2,%3};"
        : "+f"(d[0]), "+f"(d[1]), "+f"(d[2]), "+f"(d[3])
        : "r"(a[0]), "r"(a[1]), "r"(a[2]), "r"(a[3]), "r"(b0), "r"(b1));
}

// ---------------- kernel 1: W fp32 -> bf16 (+ zero g_sum) ----------------
__global__ void conv_w_kernel(const float* __restrict__ W) {
    if (blockIdx.x == 0 && threadIdx.x == 0) g_sum = 0.0f;
    size_t i = ((size_t)blockIdx.x * blockDim.x + threadIdx.x) * 4;
    float4 v = *reinterpret_cast<const float4*>(W + i);
    *reinterpret_cast<__nv_bfloat162*>(g_wbf + i)     = __floats2bfloat162_rn(v.x, v.y);
    *reinterpret_cast<__nv_bfloat162*>(g_wbf + i + 2) = __floats2bfloat162_rn(v.z, v.w);
}

// ---------------- kernel 2: normalize x rows -> bf16 (+ zero excl) ----------------
__global__ void prep_x_kernel(const float* __restrict__ x) {
    int row = blockIdx.x * 8 + (threadIdx.x >> 5);
    int lid = threadIdx.x & 31;
    const float* xr = x + (size_t)row * DIM;
    float s = 0.0f;
#pragma unroll
    for (int j = 0; j < 16; j++) { float v = xr[lid + j * 32]; s += v * v; }
#pragma unroll
    for (int o = 16; o; o >>= 1) s += __shfl_xor_sync(0xFFFFFFFFu, s, o);
    float rn = rsqrtf(s);
    __nv_bfloat16* outr = g_xbf + (size_t)row * DIM;
#pragma unroll
    for (int j = 0; j < 16; j++) {
        int d = lid + j * 32;
        outr[d] = __float2bfloat16(xr[d] * rn);
    }
    if (lid == 0) g_excl[row] = 0.0f;   // re-zero on every graph replay
}

// ---------------- kernel 3: HMMA GEMM + fused arcface epilogue ----------------
// BM=128 x BN=128, 4 warps 2x2, 64x64 warp tiles, 128 threads, 2 CTAs/SM,
// 3-stage mbarrier producer/consumer pipeline (no mainloop __syncthreads).
__global__ void __launch_bounds__(NTHREADS, 2)
arc_gemm_kernel(const int* __restrict__ target) {
    extern __shared__ char smem[];
    const uint32_t sb = smem_u32(smem);
    float* s_excl = reinterpret_cast<float*>(smem + SMEM_EXCL);
    int*   s_tg   = reinterpret_cast<int*>(smem + SMEM_TG);

    const int tid = threadIdx.x;
    const int lid = tid & 31;
    const int wid = tid >> 5;
    const int wm  = wid & 1;          // 0..1  (m, 64 rows each)
    const int wn  = wid >> 1;         // 0..1  (n, 64 cols each)
    const int rbase = blockIdx.x * BM;
    const int cbase = blockIdx.y * BN;

    if (tid == 0) {
#pragma unroll
        for (int s = 0; s < NSTAGE; s++) {
            asm volatile("mbarrier.init.shared.b64 [%0], 128;" :: "r"(FULL_MB(s))  : "memory");
            asm volatile("mbarrier.init.shared.b64 [%0], 128;" :: "r"(EMPTY_MB(s)) : "memory");
        }
    }
    // 128 threads cover all 128 rows
    s_excl[tid] = 0.0f;
    s_tg[tid]   = target[rbase + tid];
    __syncthreads();   // orders mbarrier init + s_tg/s_excl before everything

    // ---- cp.async source pointers & swizzled dst offsets, hoisted ----
    const int c_row = tid >> 3;          // 0..15, rows advance by 16 per i
    const int c_kb  = tid & 7;
    const __nv_bfloat16* xp[8];
    const __nv_bfloat16* wp[8];
    uint32_t dstoff[8];
#pragma unroll
    for (int i = 0; i < 8; i++) {
        int row = c_row + i * 16;
        xp[i] = g_xbf + (size_t)(rbase + row) * DIM + c_kb * 8;
        int c = cbase + row; c = (c < NCLS) ? c : (NCLS - 1);  // clamp hoisted
        wp[i] = g_wbf + (size_t)c * DIM + c_kb * 8;
        dstoff[i] = swz(row * 128 + c_kb * 16);
    }

    // ---- LDSM address decomposition: addr = base + rowoff + xk[kk] ----
    const uint32_t a_row  = wm * 64 + (lid & 15);
    const uint32_t a_koff = (lid >> 4) * 16;
    const uint32_t b_row  = wn * 64 + (lid & 7) + ((lid >> 4) & 1) * 8;
    const uint32_t b_koff = ((lid >> 3) & 1) * 16;
    const uint32_t maskA  = (a_row & 7) << 4;
    const uint32_t maskB  = (b_row & 7) << 4;
    uint32_t offA[4], offB[4], xka[4], xkb[4];
#pragma unroll
    for (int mt = 0; mt < 4; mt++) offA[mt] = (a_row + mt * 16) * 128;
#pragma unroll
    for (int np = 0; np < 4; np++) offB[np] = (b_row + np * 16) * 128;
#pragma unroll
    for (int kk = 0; kk < 4; kk++) {
        xka[kk] = (kk * 32 + a_koff) ^ maskA;
        xkb[kk] = (kk * 32 + b_koff) ^ maskB;
    }

    float acc[4][8][4];
#pragma unroll
    for (int mt = 0; mt < 4; mt++)
#pragma unroll
        for (int nt = 0; nt < 8; nt++)
#pragma unroll
            for (int j = 0; j < 4; j++) acc[mt][nt][j] = 0.0f;

    // ---- prologue: fill stages 0 and 1 (fresh, no empty wait) ----
#pragma unroll
    for (int pk = 0; pk < 2; pk++) {
        const int k0 = pk * BK;
        const uint32_t sa  = sb + pk * STAGE_BYTES;
        const uint32_t sbb = sa + A_STAGE;
#pragma unroll
        for (int i = 0; i < 8; i++) cp16(sa + dstoff[i], xp[i] + k0);
#pragma unroll
        for (int i = 0; i < 8; i++) cp16(sbb + dstoff[i], wp[i] + k0);
        cp_arrive(FULL_MB(pk));
    }

    uint32_t afr[4][4];
    uint32_t bfr[8][2];

    // ---- mainloop: fully unrolled; stage s=k%3, full parity (k/3)&1.
    // fills: k+2 for k in [0,5]; fi=(k+2)/3; empty wait parity (fi-1)&1,
    //        skipped for the fresh first fill of stage 2 (k+2==2).
#pragma unroll
    for (int k = 0; k < NKI; k++) {
        const int s = k % 3;
        const uint32_t abase = sb + s * STAGE_BYTES;
        const uint32_t bbase = abase + A_STAGE;

        mbar_wait(FULL_MB(s), (k / 3) & 1);

        // kk=0 fragment loads first: crossbar starts immediately
        {
            const uint32_t ax = abase + xka[0];
            const uint32_t bx = bbase + xkb[0];
#pragma unroll
            for (int mt = 0; mt < 4; mt++)
                ldm_x4(afr[mt][0], afr[mt][1], afr[mt][2], afr[mt][3], ax + offA[mt]);
#pragma unroll
            for (int np = 0; np < 4; np++) {
                uint32_t r0, r1, r2, r3;
                ldm_x4(r0, r1, r2, r3, bx + offB[np]);
                bfr[np * 2][0] = r0;     bfr[np * 2][1] = r1;
                bfr[np * 2 + 1][0] = r2; bfr[np * 2 + 1][1] = r3;
            }
        }

        // produce stage k+2
        if (k + 2 < NKI) {
            const int s2 = (k + 2) % 3;
            const int fi = (k + 2) / 3;          // 0 => fresh (stage 2 only)
            if (k + 2 > 2) mbar_wait(EMPTY_MB(s2), (fi - 1) & 1);
            const int k0 = (k + 2) * BK;
            const uint32_t sa  = sb + s2 * STAGE_BYTES;
            const uint32_t sbb = sa + A_STAGE;
#pragma unroll
            for (int i = 0; i < 8; i++) cp16(sa + dstoff[i], xp[i] + k0);
#pragma unroll
            for (int i = 0; i < 8; i++) cp16(sbb + dstoff[i], wp[i] + k0);
            cp_arrive(FULL_MB(s2));
        }

        // kk loop: MMA(kk), then LDSM(kk+1)
#pragma unroll
        for (int kk = 0; kk < 4; kk++) {
#pragma unroll
            for (int mt = 0; mt < 4; mt++)
#pragma unroll
                for (int nt = 0; nt < 8; nt++)
                    mma_bf16(acc[mt][nt], afr[mt], bfr[nt][0], bfr[nt][1]);
            if (kk < 3) {
                const uint32_t ax = abase + xka[kk + 1];
                const uint32_t bx = bbase + xkb[kk + 1];
#pragma unroll
                for (int mt = 0; mt < 4; mt++)
                    ldm_x4(afr[mt][0], afr[mt][1], afr[mt][2], afr[mt][3],
                           ax + offA[mt]);
#pragma unroll
                for (int np = 0; np < 4; np++) {
                    uint32_t r0, r1, r2, r3;
                    ldm_x4(r0, r1, r2, r3, bx + offB[np]);
                    bfr[np * 2][0] = r0;     bfr[np * 2][1] = r1;
                    bfr[np * 2 + 1][0] = r2; bfr[np * 2 + 1][1] = r3;
                }
            }
        }

        // release stage for refill (only while fills remain)
        if (k + 3 < NKI) mbar_arrive(EMPTY_MB(s));
    }

    // ---- fused epilogue from accumulator registers ----
    // c-frag: d0=(r,c0) d1=(r,c0+1) d2=(r+8,c0) d3=(r+8,c0+1); r=lid>>2, c0=2*(lid&3)
#pragma unroll
    for (int mt = 0; mt < 4; mt++) {
#pragma unroll
        for (int h = 0; h < 2; h++) {
            int rloc = wm * 64 + mt * 16 + (lid >> 2) + h * 8;
            int tg = s_tg[rloc];
            float s = 0.0f;
#pragma unroll
            for (int nt = 0; nt < 8; nt++) {
#pragma unroll
                for (int j = 0; j < 2; j++) {
                    int c = cbase + wn * 64 + nt * 8 + 2 * (lid & 3) + j;
                    float v = acc[mt][nt][h * 2 + j];
                    if (c < NCLS) {
                        if (c == tg) g_tgt[rbase + rloc] = v;
                        else         s += __expf(S_SCALE * v);
                    }
                }
            }
            // quad reduce (lanes 4t..4t+3 share rloc)
            s += __shfl_xor_sync(0xFFFFFFFFu, s, 1);
            s += __shfl_xor_sync(0xFFFFFFFFu, s, 2);
            if ((lid & 3) == 0) atomicAdd(&s_excl[rloc], s);
        }
    }
    __syncthreads();
    atomicAdd(&g_excl[rbase + tid], s_excl[tid]);
}

// ---------------- kernel 4: parallel final reduction ----------------
__global__ void finalize_part_kernel() {
    __shared__ float red[16];
    int tid = threadIdx.x;
    int i = blockIdx.x * 512 + tid;
    float t = g_tgt[i];
    t = fminf(fmaxf(t, -1.0f + 1e-7f), 1.0f - 1e-7f);
    float num = S_SCALE * (t * MARGIN_COS - sqrtf(fmaxf(1.0f - t * t, 0.0f)) * MARGIN_SIN);
    float den = expf(num) + g_excl[i];
    float s = num - logf(den);
#pragma unroll
    for (int o = 16; o; o >>= 1) s += __shfl_xor_sync(0xFFFFFFFFu, s, o);
    if ((tid & 31) == 0) red[tid >> 5] = s;
    __syncthreads();
    if (tid < 16) {
        float v = red[tid];
#pragma unroll
        for (int o = 8; o; o >>= 1) v += __shfl_xor_sync(0xFFFFu, v, o);
        if (tid == 0) atomicAdd(&g_sum, v);
    }
}

__global__ void write_out_kernel(float* __restrict__ out) {
    out[0] = -g_sum / (float)N_ROWS;
}

// ---------------- launch ----------------
extern "C" void kernel_launch(void* const* d_in, const int* in_sizes, int n_in,
                              void* d_out, int out_size) {
    const float* x      = (const float*)d_in[0];
    const float* W      = (const float*)d_in[1];
    const int*   target = (const int*)d_in[2];
    float*       out    = (float*)d_out;

    cudaFuncSetAttribute(arc_gemm_kernel,
                         cudaFuncAttributeMaxDynamicSharedMemorySize, SMEM_TOTAL);

    conv_w_kernel<<<(int)(((size_t)NCLS * DIM) / 1024), 256>>>(W);
    prep_x_kernel<<<N_ROWS / 8, 256>>>(x);
    arc_gemm_kernel<<<dim3(MTILES, NTILES), NTHREADS, SMEM_TOTAL>>>(target);
    finalize_part_kernel<<<N_ROWS / 512, 512>>>();
    write_out_kernel<<<1, 1>>>(out);
}

// round 13
// speedup vs baseline: 1.9360x; 1.9360x over previous
#include <cuda_runtime.h>
#include <cuda_bf16.h>
#include <cstdint>
#include <cstddef>

#define DEV_INLINE __device__ __forceinline__

// ---------------- problem constants (fixed shapes) ----------------
constexpr int N_ROWS = 4096;
constexpr int DIM    = 512;
constexpr int NCLS   = 50000;
constexpr float S_SCALE    = 30.0f;
constexpr float MARGIN_COS = 0.9210609940028851f;  // cos(0.4)
constexpr float MARGIN_SIN = 0.3894183423086505f;  // sin(0.4)

// ---------------- GEMM tiling ----------------
constexpr int BM = 128;
constexpr int BN = 128;
constexpr int BK = 64;                 // 64 bf16 = 128B rows (SW128 atom)
constexpr int NKI = DIM / BK;          // 8 k-iterations per tile
constexpr int NSTAGE = 3;
constexpr int MTILES = N_ROWS / BM;                  // 32 (m fastest)
constexpr int NTILES = (NCLS + BN - 1) / BN;         // 391 (last masked)
constexpr int TOTAL_TILES = MTILES * NTILES;         // 12512
constexpr int GRID_P = 304;            // 152 SMs x 2 resident CTAs (GB300)

constexpr uint32_t A_STAGE = BM * 128;               // 16384
constexpr uint32_t B_STAGE = BN * 128;               // 16384
constexpr uint32_t STAGE_BYTES = A_STAGE + B_STAGE;  // 32768
constexpr uint32_t SMEM_MBAR = NSTAGE * STAGE_BYTES;         // 98304
constexpr uint32_t SMEM_TOTAL = SMEM_MBAR + NSTAGE * 16;     // 98352 (x2 CTA)

// mbar layout: full[s] at SMEM_MBAR + s*16, empty[s] at +8
#define FULL_MB(s)  (sb + SMEM_MBAR + (uint32_t)(s) * 16)
#define EMPTY_MB(s) (sb + SMEM_MBAR + (uint32_t)(s) * 16 + 8)

// ---------------- device scratch (allocation-free rule) ----------------
__device__ __nv_bfloat16 g_xbf[(size_t)N_ROWS * DIM];   // normalized x, bf16
__device__ __nv_bfloat16 g_wbf[(size_t)NCLS * DIM];     // W, bf16 (51MB, mostly L2)
__device__ float g_excl[N_ROWS];
__device__ float g_tgt[N_ROWS];
__device__ float g_sum;

// ---------------- helpers ----------------
DEV_INLINE uint32_t smem_u32(const void* p) { return (uint32_t)__cvta_generic_to_shared(p); }
DEV_INLINE uint32_t swz(uint32_t o) { return o ^ ((o >> 3) & 0x70); }

DEV_INLINE void cp16(uint32_t dst, const void* src) {
    asm volatile("cp.async.cg.shared.global [%0], [%1], 16;" :: "r"(dst), "l"(src));
}

DEV_INLINE void cp_arrive(uint32_t mbar) {
    asm volatile("cp.async.mbarrier.arrive.noinc.shared.b64 [%0];"
                 :: "r"(mbar) : "memory");
}

DEV_INLINE void mbar_arrive(uint32_t mbar) {
    asm volatile("mbarrier.arrive.shared.b64 _, [%0];" :: "r"(mbar) : "memory");
}

DEV_INLINE void mbar_wait(uint32_t mbar, uint32_t parity) {
    asm volatile(
        "{\n\t.reg .pred P1;\n\t"
        "WL_%=:\n\t"
        "mbarrier.try_wait.parity.acquire.cta.shared::cta.b64 P1, [%0], %1, 0x989680;\n\t"
        "@P1 bra.uni WD_%=;\n\t"
        "bra.uni WL_%=;\n\t"
        "WD_%=:\n\t}"
        :: "r"(mbar), "r"(parity) : "memory");
}

DEV_INLINE void ldm_x4(uint32_t& r0, uint32_t& r1, uint32_t& r2, uint32_t& r3,
                       uint32_t addr) {
    asm volatile("ldmatrix.sync.aligned.m8n8.x4.shared.b16 {%0,%1,%2,%3}, [%4];"
                 : "=r"(r0), "=r"(r1), "=r"(r2), "=r"(r3) : "r"(addr));
}

DEV_INLINE void mma_bf16(float* d, const uint32_t* a, uint32_t b0, uint32_t b1) {
    asm volatile(
        "mma.sync.aligned.m16n8k16.row.col.f32.bf16.bf16.f32 "
        "{%0,%1,%2,%3}, {%4,%5,%6,%7}, {%8,%9}, {%0,%1,%2,%3};"
        : "+f"(d[0]), "+f"(d[1]), "+f"(d[2]), "+f"(d[3])
        : "r"(a[0]), "r"(a[1]), "r"(a[2]), "r"(a[3]), "r"(b0), "r"(b1));
}

// set per-tile cp.async source pointers (tile id -> rbase/cbase, W clamped)
DEV_INLINE void set_tile_ptrs(int tile, int c_row, int c_kb,
                              const __nv_bfloat16** xp, const __nv_bfloat16** wp) {
    const int rb = (tile & (MTILES - 1)) * BM;
    const int cb = (tile / MTILES) * BN;
#pragma unroll
    for (int i = 0; i < 4; i++) {
        int row = c_row + i * 32;
        xp[i] = g_xbf + (size_t)(rb + row) * DIM + c_kb * 8;
        int c = cb + row; c = (c < NCLS) ? c : (NCLS - 1);
        wp[i] = g_wbf + (size_t)c * DIM + c_kb * 8;
    }
}

// ---------------- kernel 1: W fp32 -> bf16 (+ zero g_sum) ----------------
__global__ void conv_w_kernel(const float* __restrict__ W) {
    if (blockIdx.x == 0 && threadIdx.x == 0) g_sum = 0.0f;
    size_t i = ((size_t)blockIdx.x * blockDim.x + threadIdx.x) * 4;
    float4 v = *reinterpret_cast<const float4*>(W + i);
    *reinterpret_cast<__nv_bfloat162*>(g_wbf + i)     = __floats2bfloat162_rn(v.x, v.y);
    *reinterpret_cast<__nv_bfloat162*>(g_wbf + i + 2) = __floats2bfloat162_rn(v.z, v.w);
}

// ---------------- kernel 2: normalize x rows -> bf16 (+ zero excl) ----------------
__global__ void prep_x_kernel(const float* __restrict__ x) {
    int row = blockIdx.x * 8 + (threadIdx.x >> 5);
    int lid = threadIdx.x & 31;
    const float* xr = x + (size_t)row * DIM;
    float s = 0.0f;
#pragma unroll
    for (int j = 0; j < 16; j++) { float v = xr[lid + j * 32]; s += v * v; }
#pragma unroll
    for (int o = 16; o; o >>= 1) s += __shfl_xor_sync(0xFFFFFFFFu, s, o);
    float rn = rsqrtf(s);
    __nv_bfloat16* outr = g_xbf + (size_t)row * DIM;
#pragma unroll
    for (int j = 0; j < 16; j++) {
        int d = lid + j * 32;
        outr[d] = __float2bfloat16(xr[d] * rn);
    }
    if (lid == 0) g_excl[row] = 0.0f;   // re-zero on every graph replay
}

// ---------------- kernel 3: persistent HMMA GEMM + fused arcface epilogue ----
// BM=BN=128, 8 warps 2x4, 64x32 warp tiles, 2 CTAs/SM, 3-stage mbarrier
// pipeline running CONTINUOUSLY across ~41 tiles per CTA (no per-tile restart).
__global__ void __launch_bounds__(256, 2)
arc_gemm_kernel(const int* __restrict__ target) {
    extern __shared__ char smem[];
    const uint32_t sb = smem_u32(smem);

    const int tid = threadIdx.x;
    const int lid = tid & 31;
    const int wid = tid >> 5;
    const int wm  = wid & 1;          // 0..1  (m, 64 rows each)
    const int wn  = wid >> 1;         // 0..3  (n, 32 cols each)

    if (tid == 0) {
#pragma unroll
        for (int s = 0; s < NSTAGE; s++) {
            asm volatile("mbarrier.init.shared.b64 [%0], 256;" :: "r"(FULL_MB(s))  : "memory");
            asm volatile("mbarrier.init.shared.b64 [%0], 256;" :: "r"(EMPTY_MB(s)) : "memory");
        }
    }
    __syncthreads();   // mbarrier init visible before any arrive/wait

    const int bid = blockIdx.x;
    const int my_ntiles = (TOTAL_TILES - bid + GRID_P - 1) / GRID_P;

    // ---- cp.async dst offsets (tile-independent) + source pointers ----
    const int c_row = tid >> 3;          // 0..31, rows advance by 32 per i
    const int c_kb  = tid & 7;
    uint32_t dstoff[4];
#pragma unroll
    for (int i = 0; i < 4; i++)
        dstoff[i] = swz((c_row + i * 32) * 128 + c_kb * 16);

    const __nv_bfloat16* xp[4];
    const __nv_bfloat16* wp[4];
    set_tile_ptrs(bid, c_row, c_kb, xp, wp);   // tile for t=0

    // ---- LDSM address decomposition: addr = stage_base + rowoff + xk[kk] ----
    const uint32_t a_row  = wm * 64 + (lid & 15);
    const uint32_t a_koff = (lid >> 4) * 16;
    const uint32_t b_row  = wn * 32 + (lid & 7) + ((lid >> 4) & 1) * 8;
    const uint32_t b_koff = ((lid >> 3) & 1) * 16;
    const uint32_t maskA  = (a_row & 7) << 4;
    const uint32_t maskB  = (b_row & 7) << 4;
    uint32_t offA[4], offB[2], xka[4], xkb[4];
#pragma unroll
    for (int mt = 0; mt < 4; mt++) offA[mt] = (a_row + mt * 16) * 128;
#pragma unroll
    for (int np = 0; np < 2; np++) offB[np] = (b_row + np * 16) * 128;
#pragma unroll
    for (int kk = 0; kk < 4; kk++) {
        xka[kk] = (kk * 32 + a_koff) ^ maskA;
        xkb[kk] = (kk * 32 + b_koff) ^ maskB;
    }

    float acc[4][4][4];
#pragma unroll
    for (int mt = 0; mt < 4; mt++)
#pragma unroll
        for (int nt = 0; nt < 4; nt++)
#pragma unroll
            for (int j = 0; j < 4; j++) acc[mt][nt][j] = 0.0f;

    // ---- pipeline cursors ----
    // consumer: cs/cph starts (0,0). producer: ps/pph starts phase 1 so the
    // first empty-wait on each fresh stage passes immediately (canonical trick).
    int cs = 0, cph = 0;
    int ps = 0, pph = 1;

    // ---- prologue: fill stages 0,1 (gk=0,1 of tile 0) ----
#pragma unroll
    for (int pk = 0; pk < 2; pk++) {
        mbar_wait(EMPTY_MB(ps), pph);            // passes (fresh, phase=1)
        const int k0 = pk * BK;
        const uint32_t sa  = sb + ps * STAGE_BYTES;
        const uint32_t sbb = sa + A_STAGE;
#pragma unroll
        for (int i = 0; i < 4; i++) cp16(sa + dstoff[i], xp[i] + k0);
#pragma unroll
        for (int i = 0; i < 4; i++) cp16(sbb + dstoff[i], wp[i] + k0);
        cp_arrive(FULL_MB(ps));
        if (++ps == NSTAGE) { ps = 0; pph ^= 1; }
    }

    uint32_t afr[4][4];
    uint32_t bfr[4][2];

    int tile = bid;           // consumer-view tile id
    for (int t = 0; t < my_ntiles; t++) {
        const int rbase = (tile & (MTILES - 1)) * BM;
        const int cbase = (tile / MTILES) * BN;
        const bool has_next = (t + 1 < my_ntiles);

#pragma unroll
        for (int k = 0; k < NKI; k++) {
            const uint32_t abase = sb + cs * STAGE_BYTES;
            const uint32_t bbase = abase + A_STAGE;

            mbar_wait(FULL_MB(cs), cph);

            // kk=0 fragment loads first: crossbar starts immediately
            {
                const uint32_t ax = abase + xka[0];
                const uint32_t bx = bbase + xkb[0];
#pragma unroll
                for (int mt = 0; mt < 4; mt++)
                    ldm_x4(afr[mt][0], afr[mt][1], afr[mt][2], afr[mt][3],
                           ax + offA[mt]);
#pragma unroll
                for (int np = 0; np < 2; np++) {
                    uint32_t r0, r1, r2, r3;
                    ldm_x4(r0, r1, r2, r3, bx + offB[np]);
                    bfr[np * 2][0] = r0;     bfr[np * 2][1] = r1;
                    bfr[np * 2 + 1][0] = r2; bfr[np * 2 + 1][1] = r3;
                }
            }

            // produce gk+2: same tile for k<=5; next tile k0/k1 for k==6/7
            const bool do_fill = (k < 6) ? true : has_next;
            if (do_fill) {
                if (k == 6) set_tile_ptrs(tile + GRID_P, c_row, c_kb, xp, wp);
                const int kf = (k + 2) & 7;      // fill k-index within its tile
                mbar_wait(EMPTY_MB(ps), pph);
                const int k0 = kf * BK;
                const uint32_t sa  = sb + ps * STAGE_BYTES;
                const uint32_t sbb = sa + A_STAGE;
#pragma unroll
                for (int i = 0; i < 4; i++) cp16(sa + dstoff[i], xp[i] + k0);
#pragma unroll
                for (int i = 0; i < 4; i++) cp16(sbb + dstoff[i], wp[i] + k0);
                cp_arrive(FULL_MB(ps));
                if (++ps == NSTAGE) { ps = 0; pph ^= 1; }
            }

            // kk loop: MMA(kk), then LDSM(kk+1)
#pragma unroll
            for (int kk = 0; kk < 4; kk++) {
#pragma unroll
                for (int mt = 0; mt < 4; mt++)
#pragma unroll
                    for (int nt = 0; nt < 4; nt++)
                        mma_bf16(acc[mt][nt], afr[mt], bfr[nt][0], bfr[nt][1]);
                if (kk < 3) {
                    const uint32_t ax = abase + xka[kk + 1];
                    const uint32_t bx = bbase + xkb[kk + 1];
#pragma unroll
                    for (int mt = 0; mt < 4; mt++)
                        ldm_x4(afr[mt][0], afr[mt][1], afr[mt][2], afr[mt][3],
                               ax + offA[mt]);
#pragma unroll
                    for (int np = 0; np < 2; np++) {
                        uint32_t r0, r1, r2, r3;
                        ldm_x4(r0, r1, r2, r3, bx + offB[np]);
                        bfr[np * 2][0] = r0;     bfr[np * 2][1] = r1;
                        bfr[np * 2 + 1][0] = r2; bfr[np * 2 + 1][1] = r3;
                    }
                }
            }

            // release stage (overlaps next tile's in-flight prefetch)
            mbar_arrive(EMPTY_MB(cs));
            if (++cs == NSTAGE) { cs = 0; cph ^= 1; }
        }

        // ---- per-tile epilogue: registers + global atomics only (no sync);
        // runs UNDER the already-issued cp.asyncs for the next tile.
#pragma unroll
        for (int mt = 0; mt < 4; mt++) {
#pragma unroll
            for (int h = 0; h < 2; h++) {
                int rloc = wm * 64 + mt * 16 + (lid >> 2) + h * 8;
                int grow = rbase + rloc;
                int tg = __ldg(target + grow);
                float s = 0.0f;
#pragma unroll
                for (int nt = 0; nt < 4; nt++) {
#pragma unroll
                    for (int j = 0; j < 2; j++) {
                        int c = cbase + wn * 32 + nt * 8 + 2 * (lid & 3) + j;
                        float v = acc[mt][nt][h * 2 + j];
                        if (c < NCLS) {
                            if (c == tg) g_tgt[grow] = v;
                            else         s += __expf(S_SCALE * v);
                        }
                        acc[mt][nt][h * 2 + j] = 0.0f;   // reset for next tile
                    }
                }
                // quad reduce (lanes 4t..4t+3 share grow), one atomic per quad
                s += __shfl_xor_sync(0xFFFFFFFFu, s, 1);
                s += __shfl_xor_sync(0xFFFFFFFFu, s, 2);
                if ((lid & 3) == 0) atomicAdd(&g_excl[grow], s);
            }
        }
        tile += GRID_P;
    }
}

// ---------------- kernel 4: parallel final reduction ----------------
__global__ void finalize_part_kernel() {
    __shared__ float red[16];
    int tid = threadIdx.x;
    int i = blockIdx.x * 512 + tid;
    float t = g_tgt[i];
    t = fminf(fmaxf(t, -1.0f + 1e-7f), 1.0f - 1e-7f);
    float num = S_SCALE * (t * MARGIN_COS - sqrtf(fmaxf(1.0f - t * t, 0.0f)) * MARGIN_SIN);
    float den = expf(num) + g_excl[i];
    float s = num - logf(den);
#pragma unroll
    for (int o = 16; o; o >>= 1) s += __shfl_xor_sync(0xFFFFFFFFu, s, o);
    if ((tid & 31) == 0) red[tid >> 5] = s;
    __syncthreads();
    if (tid < 16) {
        float v = red[tid];
#pragma unroll
        for (int o = 8; o; o >>= 1) v += __shfl_xor_sync(0xFFFFu, v, o);
        if (tid == 0) atomicAdd(&g_sum, v);
    }
}

__global__ void write_out_kernel(float* __restrict__ out) {
    out[0] = -g_sum / (float)N_ROWS;
}

// ---------------- launch ----------------
extern "C" void kernel_launch(void* const* d_in, const int* in_sizes, int n_in,
                              void* d_out, int out_size) {
    const float* x      = (const float*)d_in[0];
    const float* W      = (const float*)d_in[1];
    const int*   target = (const int*)d_in[2];
    float*       out    = (float*)d_out;

    cudaFuncSetAttribute(arc_gemm_kernel,
                         cudaFuncAttributeMaxDynamicSharedMemorySize, SMEM_TOTAL);

    conv_w_kernel<<<(int)(((size_t)NCLS * DIM) / 1024), 256>>>(W);
    prep_x_kernel<<<N_ROWS / 8, 256>>>(x);
    arc_gemm_kernel<<<GRID_P, 256, SMEM_TOTAL>>>(target);
    finalize_part_kernel<<<N_ROWS / 512, 512>>>();
    write_out_kernel<<<1, 1>>>(out);
}

// round 14
// speedup vs baseline: 2.2935x; 1.1846x over previous
#include <cuda_runtime.h>
#include <cuda_bf16.h>
#include <cstdint>
#include <cstddef>

#define DEV_INLINE __device__ __forceinline__

// ---------------- problem constants (fixed shapes) ----------------
constexpr int N_ROWS = 4096;
constexpr int DIM    = 512;
constexpr int NCLS   = 50000;
constexpr float S_SCALE    = 30.0f;
constexpr float MARGIN_COS = 0.9210609940028851f;  // cos(0.4)
constexpr float MARGIN_SIN = 0.3894183423086505f;  // sin(0.4)

// ---------------- GEMM tiling ----------------
constexpr int BM = 128;
constexpr int BN = 128;
constexpr int BK = 64;                 // 64 bf16 = 128B rows (SW128 atom)
constexpr int NKI = DIM / BK;          // 8 k-iterations
constexpr int NSTAGE = 3;
constexpr int MTILES = N_ROWS / BM;                  // 32
constexpr int NTILES = (NCLS + BN - 1) / BN;         // 391 (last masked)

constexpr uint32_t A_STAGE = BM * 128;               // 16384
constexpr uint32_t B_STAGE = BN * 128;               // 16384
constexpr uint32_t STAGE_BYTES = A_STAGE + B_STAGE;  // 32768
constexpr uint32_t SMEM_MBAR = NSTAGE * STAGE_BYTES;         // 98304
constexpr uint32_t SMEM_TOTAL = SMEM_MBAR + NSTAGE * 16;     // 98352 (x2 CTA)

// mbar layout: full[s] at SMEM_MBAR + s*16, empty[s] at +8
#define FULL_MB(s)  (sb + SMEM_MBAR + (s) * 16)
#define EMPTY_MB(s) (sb + SMEM_MBAR + (s) * 16 + 8)

// ---------------- device scratch (allocation-free rule) ----------------
__device__ __nv_bfloat16 g_xbf[(size_t)N_ROWS * DIM];   // normalized x, bf16
__device__ __nv_bfloat16 g_wbf[(size_t)NCLS * DIM];     // W, bf16 (51MB, mostly L2)
__device__ float g_excl[N_ROWS];    // holds FULL row exp-sum; target term subtracted in finalize
__device__ float g_sum;

// ---------------- helpers ----------------
DEV_INLINE uint32_t smem_u32(const void* p) { return (uint32_t)__cvta_generic_to_shared(p); }
DEV_INLINE uint32_t swz(uint32_t o) { return o ^ ((o >> 3) & 0x70); }

DEV_INLINE void cp16(uint32_t dst, const void* src) {
    asm volatile("cp.async.cg.shared.global [%0], [%1], 16;" :: "r"(dst), "l"(src));
}

DEV_INLINE void cp_arrive(uint32_t mbar) {
    asm volatile("cp.async.mbarrier.arrive.noinc.shared.b64 [%0];"
                 :: "r"(mbar) : "memory");
}

DEV_INLINE void mbar_arrive(uint32_t mbar) {
    asm volatile("mbarrier.arrive.shared.b64 _, [%0];" :: "r"(mbar) : "memory");
}

DEV_INLINE void mbar_wait(uint32_t mbar, uint32_t parity) {
    asm volatile(
        "{\n\t.reg .pred P1;\n\t"
        "WL_%=:\n\t"
        "mbarrier.try_wait.parity.acquire.cta.shared::cta.b64 P1, [%0], %1, 0x989680;\n\t"
        "@P1 bra.uni WD_%=;\n\t"
        "bra.uni WL_%=;\n\t"
        "WD_%=:\n\t}"
        :: "r"(mbar), "r"(parity) : "memory");
}

DEV_INLINE void ldm_x4(uint32_t& r0, uint32_t& r1, uint32_t& r2, uint32_t& r3,
                       uint32_t addr) {
    asm volatile("ldmatrix.sync.aligned.m8n8.x4.shared.b16 {%0,%1,%2,%3}, [%4];"
                 : "=r"(r0), "=r"(r1), "=r"(r2), "=r"(r3) : "r"(addr));
}

DEV_INLINE void mma_bf16(float* d, const uint32_t* a, uint32_t b0, uint32_t b1) {
    asm volatile(
        "mma.sync.aligned.m16n8k16.row.col.f32.bf16.bf16.f32 "
        "{%0,%1,%2,%3}, {%4,%5,%6,%7}, {%8,%9}, {%0,%1,%2,%3};"
        : "+f"(d[0]), "+f"(d[1]), "+f"(d[2]), "+f"(d[3])
        : "r"(a[0]), "r"(a[1]), "r"(a[2]), "r"(a[3]), "r"(b0), "r"(b1));
}

// ---------------- kernel 1: W fp32 -> bf16 (+ zero g_sum) ----------------
__global__ void conv_w_kernel(const float* __restrict__ W) {
    if (blockIdx.x == 0 && threadIdx.x == 0) g_sum = 0.0f;
    size_t i = ((size_t)blockIdx.x * blockDim.x + threadIdx.x) * 4;
    float4 v = *reinterpret_cast<const float4*>(W + i);
    *reinterpret_cast<__nv_bfloat162*>(g_wbf + i)     = __floats2bfloat162_rn(v.x, v.y);
    *reinterpret_cast<__nv_bfloat162*>(g_wbf + i + 2) = __floats2bfloat162_rn(v.z, v.w);
}

// ---------------- kernel 2: normalize x rows -> bf16 (+ zero excl) ----------------
__global__ void prep_x_kernel(const float* __restrict__ x) {
    int row = blockIdx.x * 8 + (threadIdx.x >> 5);
    int lid = threadIdx.x & 31;
    const float* xr = x + (size_t)row * DIM;
    float s = 0.0f;
#pragma unroll
    for (int j = 0; j < 16; j++) { float v = xr[lid + j * 32]; s += v * v; }
#pragma unroll
    for (int o = 16; o; o >>= 1) s += __shfl_xor_sync(0xFFFFFFFFu, s, o);
    float rn = rsqrtf(s);
    __nv_bfloat16* outr = g_xbf + (size_t)row * DIM;
#pragma unroll
    for (int j = 0; j < 16; j++) {
        int d = lid + j * 32;
        outr[d] = __float2bfloat16(xr[d] * rn);
    }
    if (lid == 0) g_excl[row] = 0.0f;   // re-zero on every graph replay
}

// ---------------- kernel 3: HMMA GEMM + branch-free exp-sum epilogue ----------
// BM=128 x BN=128, 8 warps 2x4, 64x32 warp tiles, 2 CTAs/SM, 3-stage mbarrier
// pipeline (no mainloop __syncthreads). Epilogue sums exp(S*v) over ALL classes;
// the target term is subtracted later in finalize (no per-element branching).
__global__ void __launch_bounds__(256, 2)
arc_gemm_kernel() {
    extern __shared__ char smem[];
    const uint32_t sb = smem_u32(smem);

    const int tid = threadIdx.x;
    const int lid = tid & 31;
    const int wid = tid >> 5;
    const int wm  = wid & 1;          // 0..1  (m, 64 rows each)
    const int wn  = wid >> 1;         // 0..3  (n, 32 cols each)
    const int rbase = blockIdx.x * BM;
    const int cbase = blockIdx.y * BN;

    if (tid == 0) {
#pragma unroll
        for (int s = 0; s < NSTAGE; s++) {
            asm volatile("mbarrier.init.shared.b64 [%0], 256;" :: "r"(FULL_MB(s))  : "memory");
            asm volatile("mbarrier.init.shared.b64 [%0], 256;" :: "r"(EMPTY_MB(s)) : "memory");
        }
    }
    __syncthreads();   // mbarrier init visible before any arrive/wait

    // ---- cp.async source pointers & swizzled dst offsets, hoisted ----
    const int c_row = tid >> 3;          // rows advance by 32 per i
    const int c_kb  = tid & 7;
    const __nv_bfloat16* xp[4];
    const __nv_bfloat16* wp[4];
    uint32_t dstoff[4];
#pragma unroll
    for (int i = 0; i < 4; i++) {
        int row = c_row + i * 32;
        xp[i] = g_xbf + (size_t)(rbase + row) * DIM + c_kb * 8;
        int c = cbase + row; c = (c < NCLS) ? c : (NCLS - 1);  // clamp hoisted
        wp[i] = g_wbf + (size_t)c * DIM + c_kb * 8;
        dstoff[i] = swz(row * 128 + c_kb * 16);
    }

    // ---- LDSM address decomposition: addr = base + rowoff + xk[kk] ----
    const uint32_t a_row  = wm * 64 + (lid & 15);
    const uint32_t a_koff = (lid >> 4) * 16;
    const uint32_t b_row  = wn * 32 + (lid & 7) + ((lid >> 4) & 1) * 8;
    const uint32_t b_koff = ((lid >> 3) & 1) * 16;
    const uint32_t maskA  = (a_row & 7) << 4;
    const uint32_t maskB  = (b_row & 7) << 4;
    uint32_t offA[4], offB[2], xka[4], xkb[4];
#pragma unroll
    for (int mt = 0; mt < 4; mt++) offA[mt] = (a_row + mt * 16) * 128;
#pragma unroll
    for (int np = 0; np < 2; np++) offB[np] = (b_row + np * 16) * 128;
#pragma unroll
    for (int kk = 0; kk < 4; kk++) {
        xka[kk] = (kk * 32 + a_koff) ^ maskA;
        xkb[kk] = (kk * 32 + b_koff) ^ maskB;
    }

    float acc[4][4][4];
#pragma unroll
    for (int mt = 0; mt < 4; mt++)
#pragma unroll
        for (int nt = 0; nt < 4; nt++)
#pragma unroll
            for (int j = 0; j < 4; j++) acc[mt][nt][j] = 0.0f;

    // ---- prologue: fill stages 0 and 1 (fresh, no empty wait) ----
#pragma unroll
    for (int pk = 0; pk < 2; pk++) {
        const int k0 = pk * BK;
        const uint32_t sa  = sb + pk * STAGE_BYTES;
        const uint32_t sbb = sa + A_STAGE;
#pragma unroll
        for (int i = 0; i < 4; i++) cp16(sa + dstoff[i], xp[i] + k0);
#pragma unroll
        for (int i = 0; i < 4; i++) cp16(sbb + dstoff[i], wp[i] + k0);
        cp_arrive(FULL_MB(pk));
    }

    uint32_t afr[4][4];
    uint32_t bfr[4][2];

    // ---- mainloop: fully unrolled; stage s=k%3, full parity (k/3)&1.
#pragma unroll
    for (int k = 0; k < NKI; k++) {
        const int s = k % 3;
        const uint32_t abase = sb + s * STAGE_BYTES;
        const uint32_t bbase = abase + A_STAGE;

        mbar_wait(FULL_MB(s), (k / 3) & 1);

        // kk=0 fragment loads first: crossbar starts immediately
        {
            const uint32_t ax = abase + xka[0];
            const uint32_t bx = bbase + xkb[0];
#pragma unroll
            for (int mt = 0; mt < 4; mt++)
                ldm_x4(afr[mt][0], afr[mt][1], afr[mt][2], afr[mt][3], ax + offA[mt]);
#pragma unroll
            for (int np = 0; np < 2; np++) {
                uint32_t r0, r1, r2, r3;
                ldm_x4(r0, r1, r2, r3, bx + offB[np]);
                bfr[np * 2][0] = r0;     bfr[np * 2][1] = r1;
                bfr[np * 2 + 1][0] = r2; bfr[np * 2 + 1][1] = r3;
            }
        }

        // produce stage k+2
        if (k + 2 < NKI) {
            const int s2 = (k + 2) % 3;
            const int fi = (k + 2) / 3;          // 0 => fresh (stage 2 only)
            if (k + 2 > 2) mbar_wait(EMPTY_MB(s2), (fi - 1) & 1);
            const int k0 = (k + 2) * BK;
            const uint32_t sa  = sb + s2 * STAGE_BYTES;
            const uint32_t sbb = sa + A_STAGE;
#pragma unroll
            for (int i = 0; i < 4; i++) cp16(sa + dstoff[i], xp[i] + k0);
#pragma unroll
            for (int i = 0; i < 4; i++) cp16(sbb + dstoff[i], wp[i] + k0);
            cp_arrive(FULL_MB(s2));
        }

        // kk loop: MMA(kk), then LDSM(kk+1)
#pragma unroll
        for (int kk = 0; kk < 4; kk++) {
#pragma unroll
            for (int mt = 0; mt < 4; mt++)
#pragma unroll
                for (int nt = 0; nt < 4; nt++)
                    mma_bf16(acc[mt][nt], afr[mt], bfr[nt][0], bfr[nt][1]);
            if (kk < 3) {
                const uint32_t ax = abase + xka[kk + 1];
                const uint32_t bx = bbase + xkb[kk + 1];
#pragma unroll
                for (int mt = 0; mt < 4; mt++)
                    ldm_x4(afr[mt][0], afr[mt][1], afr[mt][2], afr[mt][3],
                           ax + offA[mt]);
#pragma unroll
                for (int np = 0; np < 2; np++) {
                    uint32_t r0, r1, r2, r3;
                    ldm_x4(r0, r1, r2, r3, bx + offB[np]);
                    bfr[np * 2][0] = r0;     bfr[np * 2][1] = r1;
                    bfr[np * 2 + 1][0] = r2; bfr[np * 2 + 1][1] = r3;
                }
            }
        }

        // release stage for refill (only while fills remain)
        if (k + 3 < NKI) mbar_arrive(EMPTY_MB(s));
    }

    // ---- branch-free epilogue: full exp-sum, one RED per quad, no syncs ----
    // c-frag: d0=(r,c0) d1=(r,c0+1) d2=(r+8,c0) d3=(r+8,c0+1); r=lid>>2, c0=2*(lid&3)
    if (cbase + BN <= NCLS) {
        // fast path: all 128 columns valid (390 of 391 tiles)
#pragma unroll
        for (int mt = 0; mt < 4; mt++) {
#pragma unroll
            for (int h = 0; h < 2; h++) {
                int grow = rbase + wm * 64 + mt * 16 + (lid >> 2) + h * 8;
                float s = 0.0f;
#pragma unroll
                for (int nt = 0; nt < 4; nt++) {
                    s += __expf(S_SCALE * acc[mt][nt][h * 2]);
                    s += __expf(S_SCALE * acc[mt][nt][h * 2 + 1]);
                }
                s += __shfl_xor_sync(0xFFFFFFFFu, s, 1);
                s += __shfl_xor_sync(0xFFFFFFFFu, s, 2);
                if ((lid & 3) == 0) atomicAdd(&g_excl[grow], s);
            }
        }
    } else {
        // tail tile: mask c >= NCLS (clamp-loaded duplicates)
#pragma unroll
        for (int mt = 0; mt < 4; mt++) {
#pragma unroll
            for (int h = 0; h < 2; h++) {
                int grow = rbase + wm * 64 + mt * 16 + (lid >> 2) + h * 8;
                float s = 0.0f;
#pragma unroll
                for (int nt = 0; nt < 4; nt++) {
#pragma unroll
                    for (int j = 0; j < 2; j++) {
                        int c = cbase + wn * 32 + nt * 8 + 2 * (lid & 3) + j;
                        if (c < NCLS) s += __expf(S_SCALE * acc[mt][nt][h * 2 + j]);
                    }
                }
                s += __shfl_xor_sync(0xFFFFFFFFu, s, 1);
                s += __shfl_xor_sync(0xFFFFFFFFu, s, 2);
                if ((lid & 3) == 0) atomicAdd(&g_excl[grow], s);
            }
        }
    }
}

// ---------------- kernel 4: finalize — fp32 target dot + loss reduction -----
// One warp per row: recompute target cosine t = x_i . W[tg] / ||x_i|| in fp32
// (exact), subtract its exp term from the full sum, accumulate the loss.
__global__ void finalize_part_kernel(const float* __restrict__ x,
                                     const float* __restrict__ W,
                                     const int* __restrict__ target) {
    __shared__ float red[8];
    int wid = threadIdx.x >> 5, lid = threadIdx.x & 31;
    int row = blockIdx.x * 8 + wid;

    const float4* xr = reinterpret_cast<const float4*>(x + (size_t)row * DIM);
    float4 xv[4];
    float ss = 0.0f;
#pragma unroll
    for (int j = 0; j < 4; j++) {
        float4 v = xr[lid + j * 32];
        xv[j] = v;
        ss += v.x * v.x + v.y * v.y + v.z * v.z + v.w * v.w;
    }
    int tg = __ldg(target + row);
    const float4* wr = reinterpret_cast<const float4*>(W + (size_t)tg * DIM);
    float dp = 0.0f;
#pragma unroll
    for (int j = 0; j < 4; j++) {
        float4 w = wr[lid + j * 32];
        dp += xv[j].x * w.x + xv[j].y * w.y + xv[j].z * w.z + xv[j].w * w.w;
    }
#pragma unroll
    for (int o = 16; o; o >>= 1) {
        ss += __shfl_xor_sync(0xFFFFFFFFu, ss, o);
        dp += __shfl_xor_sync(0xFFFFFFFFu, dp, o);
    }
    if (lid == 0) {
        float t = dp * rsqrtf(ss);
        t = fminf(fmaxf(t, -1.0f + 1e-7f), 1.0f - 1e-7f);
        float num = S_SCALE * (t * MARGIN_COS
                               - sqrtf(fmaxf(1.0f - t * t, 0.0f)) * MARGIN_SIN);
        float excl = g_excl[row] - __expf(S_SCALE * t);   // subtract target term
        float den = expf(num) + excl;
        red[wid] = num - logf(den);
    }
    __syncthreads();
    if (threadIdx.x < 8) {
        float v = red[threadIdx.x];
#pragma unroll
        for (int o = 4; o; o >>= 1) v += __shfl_xor_sync(0xFFu, v, o);
        if (threadIdx.x == 0) atomicAdd(&g_sum, v);
    }
}

__global__ void write_out_kernel(float* __restrict__ out) {
    out[0] = -g_sum / (float)N_ROWS;
}

// ---------------- launch ----------------
extern "C" void kernel_launch(void* const* d_in, const int* in_sizes, int n_in,
                              void* d_out, int out_size) {
    const float* x      = (const float*)d_in[0];
    const float* W      = (const float*)d_in[1];
    const int*   target = (const int*)d_in[2];
    float*       out    = (float*)d_out;

    cudaFuncSetAttribute(arc_gemm_kernel,
                         cudaFuncAttributeMaxDynamicSharedMemorySize, SMEM_TOTAL);

    conv_w_kernel<<<(int)(((size_t)NCLS * DIM) / 1024), 256>>>(W);
    prep_x_kernel<<<N_ROWS / 8, 256>>>(x);
    arc_gemm_kernel<<<dim3(MTILES, NTILES), 256, SMEM_TOTAL>>>();
    finalize_part_kernel<<<N_ROWS / 8, 256>>>(x, W, target);
    write_out_kernel<<<1, 1>>>(out);
}

// round 15
// speedup vs baseline: 2.3113x; 1.0078x over previous
#include <cuda_runtime.h>
#include <cuda_bf16.h>
#include <cstdint>
#include <cstddef>

#define DEV_INLINE __device__ __forceinline__

// ---------------- problem constants (fixed shapes) ----------------
constexpr int N_ROWS = 4096;
constexpr int DIM    = 512;
constexpr int NCLS   = 50000;
constexpr float S_SCALE    = 30.0f;
constexpr float MARGIN_COS = 0.9210609940028851f;  // cos(0.4)
constexpr float MARGIN_SIN = 0.3894183423086505f;  // sin(0.4)

// ---------------- GEMM tiling ----------------
constexpr int BM = 128;
constexpr int BN = 128;
constexpr int BK = 64;                 // 64 bf16 = 128B rows (SW128 atom)
constexpr int NKI = DIM / BK;          // 8 k-iterations
constexpr int NSTAGE = 3;
constexpr int MTILES = N_ROWS / BM;                  // 32
constexpr int NTILES = (NCLS + BN - 1) / BN;         // 391 (last masked)

constexpr uint32_t A_STAGE = BM * 128;               // 16384
constexpr uint32_t B_STAGE = BN * 128;               // 16384
constexpr uint32_t STAGE_BYTES = A_STAGE + B_STAGE;  // 32768
constexpr uint32_t SMEM_MBAR = NSTAGE * STAGE_BYTES;         // 98304
constexpr uint32_t SMEM_TOTAL = SMEM_MBAR + NSTAGE * 16;     // 98352 (x2 CTA)

// mbar layout: full[s] at SMEM_MBAR + s*16, empty[s] at +8
#define FULL_MB(s)  (sb + SMEM_MBAR + (s) * 16)
#define EMPTY_MB(s) (sb + SMEM_MBAR + (s) * 16 + 8)

// ---------------- device scratch (allocation-free rule) ----------------
__device__ __nv_bfloat16 g_xbf[(size_t)N_ROWS * DIM];   // normalized x, bf16
__device__ __nv_bfloat16 g_wbf[(size_t)NCLS * DIM];     // W, bf16 (51MB, mostly L2)
__device__ float g_excl[N_ROWS];    // FULL row exp-sum; target term subtracted in finalize
__device__ float g_tgt[N_ROWS];     // clamped fp32 target cosine (computed in prep_x)
__device__ float g_sum;

// ---------------- helpers ----------------
DEV_INLINE uint32_t smem_u32(const void* p) { return (uint32_t)__cvta_generic_to_shared(p); }
DEV_INLINE uint32_t swz(uint32_t o) { return o ^ ((o >> 3) & 0x70); }

DEV_INLINE void cp16(uint32_t dst, const void* src) {
    asm volatile("cp.async.cg.shared.global [%0], [%1], 16;" :: "r"(dst), "l"(src));
}

DEV_INLINE void cp_arrive(uint32_t mbar) {
    asm volatile("cp.async.mbarrier.arrive.noinc.shared.b64 [%0];"
                 :: "r"(mbar) : "memory");
}

DEV_INLINE void mbar_arrive(uint32_t mbar) {
    asm volatile("mbarrier.arrive.shared.b64 _, [%0];" :: "r"(mbar) : "memory");
}

DEV_INLINE void mbar_wait(uint32_t mbar, uint32_t parity) {
    asm volatile(
        "{\n\t.reg .pred P1;\n\t"
        "WL_%=:\n\t"
        "mbarrier.try_wait.parity.acquire.cta.shared::cta.b64 P1, [%0], %1, 0x989680;\n\t"
        "@P1 bra.uni WD_%=;\n\t"
        "bra.uni WL_%=;\n\t"
        "WD_%=:\n\t}"
        :: "r"(mbar), "r"(parity) : "memory");
}

DEV_INLINE void ldm_x4(uint32_t& r0, uint32_t& r1, uint32_t& r2, uint32_t& r3,
                       uint32_t addr) {
    asm volatile("ldmatrix.sync.aligned.m8n8.x4.shared.b16 {%0,%1,%2,%3}, [%4];"
                 : "=r"(r0), "=r"(r1), "=r"(r2), "=r"(r3) : "r"(addr));
}

DEV_INLINE void mma_bf16(float* d, const uint32_t* a, uint32_t b0, uint32_t b1) {
    asm volatile(
        "mma.sync.aligned.m16n8k16.row.col.f32.bf16.bf16.f32 "
        "{%0,%1,%2,%3}, {%4,%5,%6,%7}, {%8,%9}, {%0,%1,%2,%3};"
        : "+f"(d[0]), "+f"(d[1]), "+f"(d[2]), "+f"(d[3])
        : "r"(a[0]), "r"(a[1]), "r"(a[2]), "r"(a[3]), "r"(b0), "r"(b1));
}

// ---------------- kernel 1: W fp32 -> bf16 (+ zero g_sum) ----------------
// 8 floats per thread, one 16B bf16 store.
__global__ void conv_w_kernel(const float* __restrict__ W) {
    if (blockIdx.x == 0 && threadIdx.x == 0) g_sum = 0.0f;
    size_t i = ((size_t)blockIdx.x * blockDim.x + threadIdx.x) * 8;
    float4 a = *reinterpret_cast<const float4*>(W + i);
    float4 b = *reinterpret_cast<const float4*>(W + i + 4);
    uint4 o;
    o.x = __uint_as_float(0), o.x = 0;  // placate compiler init
    __nv_bfloat162 p0 = __floats2bfloat162_rn(a.x, a.y);
    __nv_bfloat162 p1 = __floats2bfloat162_rn(a.z, a.w);
    __nv_bfloat162 p2 = __floats2bfloat162_rn(b.x, b.y);
    __nv_bfloat162 p3 = __floats2bfloat162_rn(b.z, b.w);
    o.x = *reinterpret_cast<uint32_t*>(&p0);
    o.y = *reinterpret_cast<uint32_t*>(&p1);
    o.z = *reinterpret_cast<uint32_t*>(&p2);
    o.w = *reinterpret_cast<uint32_t*>(&p3);
    *reinterpret_cast<uint4*>(g_wbf + i) = o;
}

// ---------------- kernel 2: normalize x -> bf16, fp32 target cosine, zero excl
// One warp per row: row L2-norm, bf16 store, and exact fp32 dot with W[target].
__global__ void prep_x_kernel(const float* __restrict__ x,
                              const float* __restrict__ W,
                              const int* __restrict__ target) {
    int row = blockIdx.x * 8 + (threadIdx.x >> 5);
    int lid = threadIdx.x & 31;
    const float4* xr = reinterpret_cast<const float4*>(x + (size_t)row * DIM);
    int tg = __ldg(target + row);
    const float4* wr = reinterpret_cast<const float4*>(W + (size_t)tg * DIM);

    float4 xv[4];
    float ss = 0.0f, dp = 0.0f;
#pragma unroll
    for (int j = 0; j < 4; j++) {
        float4 v = xr[lid + j * 32];
        float4 w = wr[lid + j * 32];
        xv[j] = v;
        ss += v.x * v.x + v.y * v.y + v.z * v.z + v.w * v.w;
        dp += v.x * w.x + v.y * w.y + v.z * w.z + v.w * w.w;
    }
#pragma unroll
    for (int o = 16; o; o >>= 1) {
        ss += __shfl_xor_sync(0xFFFFFFFFu, ss, o);
        dp += __shfl_xor_sync(0xFFFFFFFFu, dp, o);
    }
    float rn = rsqrtf(ss);
    __nv_bfloat16* outr = g_xbf + (size_t)row * DIM;
#pragma unroll
    for (int j = 0; j < 4; j++) {
        float4 v = xv[j];
        __nv_bfloat162 p0 = __floats2bfloat162_rn(v.x * rn, v.y * rn);
        __nv_bfloat162 p1 = __floats2bfloat162_rn(v.z * rn, v.w * rn);
        uint32_t u0 = *reinterpret_cast<uint32_t*>(&p0);
        uint32_t u1 = *reinterpret_cast<uint32_t*>(&p1);
        uint2 o2 = make_uint2(u0, u1);
        *reinterpret_cast<uint2*>(outr + (lid + j * 32) * 4) = o2;
    }
    if (lid == 0) {
        float t = dp * rn;
        g_tgt[row]  = fminf(fmaxf(t, -1.0f + 1e-7f), 1.0f - 1e-7f);
        g_excl[row] = 0.0f;   // re-zero on every graph replay
    }
}

// ---------------- kernel 3: HMMA GEMM + branch-free exp-sum epilogue ----------
// BM=128 x BN=128, 8 warps 2x4, 64x32 warp tiles, 2 CTAs/SM, 3-stage mbarrier
// pipeline (no mainloop __syncthreads). Epilogue sums exp(S*v) over ALL classes;
// the target term is subtracted later in finalize (no per-element branching).
__global__ void __launch_bounds__(256, 2)
arc_gemm_kernel() {
    extern __shared__ char smem[];
    const uint32_t sb = smem_u32(smem);

    const int tid = threadIdx.x;
    const int lid = tid & 31;
    const int wid = tid >> 5;
    const int wm  = wid & 1;          // 0..1  (m, 64 rows each)
    const int wn  = wid >> 1;         // 0..3  (n, 32 cols each)
    const int rbase = blockIdx.x * BM;
    const int cbase = blockIdx.y * BN;

    if (tid == 0) {
#pragma unroll
        for (int s = 0; s < NSTAGE; s++) {
            asm volatile("mbarrier.init.shared.b64 [%0], 256;" :: "r"(FULL_MB(s))  : "memory");
            asm volatile("mbarrier.init.shared.b64 [%0], 256;" :: "r"(EMPTY_MB(s)) : "memory");
        }
    }
    __syncthreads();   // mbarrier init visible before any arrive/wait

    // ---- cp.async source pointers & swizzled dst offsets, hoisted ----
    const int c_row = tid >> 3;          // rows advance by 32 per i
    const int c_kb  = tid & 7;
    const __nv_bfloat16* xp[4];
    const __nv_bfloat16* wp[4];
    uint32_t dstoff[4];
#pragma unroll
    for (int i = 0; i < 4; i++) {
        int row = c_row + i * 32;
        xp[i] = g_xbf + (size_t)(rbase + row) * DIM + c_kb * 8;
        int c = cbase + row; c = (c < NCLS) ? c : (NCLS - 1);  // clamp hoisted
        wp[i] = g_wbf + (size_t)c * DIM + c_kb * 8;
        dstoff[i] = swz(row * 128 + c_kb * 16);
    }

    // ---- LDSM address decomposition: addr = base + rowoff + xk[kk] ----
    const uint32_t a_row  = wm * 64 + (lid & 15);
    const uint32_t a_koff = (lid >> 4) * 16;
    const uint32_t b_row  = wn * 32 + (lid & 7) + ((lid >> 4) & 1) * 8;
    const uint32_t b_koff = ((lid >> 3) & 1) * 16;
    const uint32_t maskA  = (a_row & 7) << 4;
    const uint32_t maskB  = (b_row & 7) << 4;
    uint32_t offA[4], offB[2], xka[4], xkb[4];
#pragma unroll
    for (int mt = 0; mt < 4; mt++) offA[mt] = (a_row + mt * 16) * 128;
#pragma unroll
    for (int np = 0; np < 2; np++) offB[np] = (b_row + np * 16) * 128;
#pragma unroll
    for (int kk = 0; kk < 4; kk++) {
        xka[kk] = (kk * 32 + a_koff) ^ maskA;
        xkb[kk] = (kk * 32 + b_koff) ^ maskB;
    }

    float acc[4][4][4];
#pragma unroll
    for (int mt = 0; mt < 4; mt++)
#pragma unroll
        for (int nt = 0; nt < 4; nt++)
#pragma unroll
            for (int j = 0; j < 4; j++) acc[mt][nt][j] = 0.0f;

    // ---- prologue: fill stages 0 and 1 (fresh, no empty wait) ----
#pragma unroll
    for (int pk = 0; pk < 2; pk++) {
        const int k0 = pk * BK;
        const uint32_t sa  = sb + pk * STAGE_BYTES;
        const uint32_t sbb = sa + A_STAGE;
#pragma unroll
        for (int i = 0; i < 4; i++) cp16(sa + dstoff[i], xp[i] + k0);
#pragma unroll
        for (int i = 0; i < 4; i++) cp16(sbb + dstoff[i], wp[i] + k0);
        cp_arrive(FULL_MB(pk));
    }

    uint32_t afr[4][4];
    uint32_t bfr[4][2];

    // ---- mainloop: fully unrolled; stage s=k%3, full parity (k/3)&1.
#pragma unroll
    for (int k = 0; k < NKI; k++) {
        const int s = k % 3;
        const uint32_t abase = sb + s * STAGE_BYTES;
        const uint32_t bbase = abase + A_STAGE;

        mbar_wait(FULL_MB(s), (k / 3) & 1);

        // kk=0 fragment loads first: crossbar starts immediately
        {
            const uint32_t ax = abase + xka[0];
            const uint32_t bx = bbase + xkb[0];
#pragma unroll
            for (int mt = 0; mt < 4; mt++)
                ldm_x4(afr[mt][0], afr[mt][1], afr[mt][2], afr[mt][3], ax + offA[mt]);
#pragma unroll
            for (int np = 0; np < 2; np++) {
                uint32_t r0, r1, r2, r3;
                ldm_x4(r0, r1, r2, r3, bx + offB[np]);
                bfr[np * 2][0] = r0;     bfr[np * 2][1] = r1;
                bfr[np * 2 + 1][0] = r2; bfr[np * 2 + 1][1] = r3;
            }
        }

        // produce stage k+2
        if (k + 2 < NKI) {
            const int s2 = (k + 2) % 3;
            const int fi = (k + 2) / 3;          // 0 => fresh (stage 2 only)
            if (k + 2 > 2) mbar_wait(EMPTY_MB(s2), (fi - 1) & 1);
            const int k0 = (k + 2) * BK;
            const uint32_t sa  = sb + s2 * STAGE_BYTES;
            const uint32_t sbb = sa + A_STAGE;
#pragma unroll
            for (int i = 0; i < 4; i++) cp16(sa + dstoff[i], xp[i] + k0);
#pragma unroll
            for (int i = 0; i < 4; i++) cp16(sbb + dstoff[i], wp[i] + k0);
            cp_arrive(FULL_MB(s2));
        }

        // kk loop: MMA(kk), then LDSM(kk+1)
#pragma unroll
        for (int kk = 0; kk < 4; kk++) {
#pragma unroll
            for (int mt = 0; mt < 4; mt++)
#pragma unroll
                for (int nt = 0; nt < 4; nt++)
                    mma_bf16(acc[mt][nt], afr[mt], bfr[nt][0], bfr[nt][1]);
            if (kk < 3) {
                const uint32_t ax = abase + xka[kk + 1];
                const uint32_t bx = bbase + xkb[kk + 1];
#pragma unroll
                for (int mt = 0; mt < 4; mt++)
                    ldm_x4(afr[mt][0], afr[mt][1], afr[mt][2], afr[mt][3],
                           ax + offA[mt]);
#pragma unroll
                for (int np = 0; np < 2; np++) {
                    uint32_t r0, r1, r2, r3;
                    ldm_x4(r0, r1, r2, r3, bx + offB[np]);
                    bfr[np * 2][0] = r0;     bfr[np * 2][1] = r1;
                    bfr[np * 2 + 1][0] = r2; bfr[np * 2 + 1][1] = r3;
                }
            }
        }

        // release stage for refill (only while fills remain)
        if (k + 3 < NKI) mbar_arrive(EMPTY_MB(s));
    }

    // ---- branch-free epilogue: full exp-sum, one RED per quad, no syncs ----
    // c-frag: d0=(r,c0) d1=(r,c0+1) d2=(r+8,c0) d3=(r+8,c0+1); r=lid>>2, c0=2*(lid&3)
    if (cbase + BN <= NCLS) {
        // fast path: all 128 columns valid (390 of 391 tiles)
#pragma unroll
        for (int mt = 0; mt < 4; mt++) {
#pragma unroll
            for (int h = 0; h < 2; h++) {
                int grow = rbase + wm * 64 + mt * 16 + (lid >> 2) + h * 8;
                float s = 0.0f;
#pragma unroll
                for (int nt = 0; nt < 4; nt++) {
                    s += __expf(S_SCALE * acc[mt][nt][h * 2]);
                    s += __expf(S_SCALE * acc[mt][nt][h * 2 + 1]);
                }
                s += __shfl_xor_sync(0xFFFFFFFFu, s, 1);
                s += __shfl_xor_sync(0xFFFFFFFFu, s, 2);
                if ((lid & 3) == 0) atomicAdd(&g_excl[grow], s);
            }
        }
    } else {
        // tail tile: mask c >= NCLS (clamp-loaded duplicates)
#pragma unroll
        for (int mt = 0; mt < 4; mt++) {
#pragma unroll
            for (int h = 0; h < 2; h++) {
                int grow = rbase + wm * 64 + mt * 16 + (lid >> 2) + h * 8;
                float s = 0.0f;
#pragma unroll
                for (int nt = 0; nt < 4; nt++) {
#pragma unroll
                    for (int j = 0; j < 2; j++) {
                        int c = cbase + wn * 32 + nt * 8 + 2 * (lid & 3) + j;
                        if (c < NCLS) s += __expf(S_SCALE * acc[mt][nt][h * 2 + j]);
                    }
                }
                s += __shfl_xor_sync(0xFFFFFFFFu, s, 1);
                s += __shfl_xor_sync(0xFFFFFFFFu, s, 2);
                if ((lid & 3) == 0) atomicAdd(&g_excl[grow], s);
            }
        }
    }
}

// ---------------- kernel 4: finalize — pure reduction over precomputed rows --
__global__ void finalize_part_kernel() {
    __shared__ float red[16];
    int tid = threadIdx.x;
    int i = blockIdx.x * 512 + tid;
    float t = g_tgt[i];   // already clamped fp32 cosine
    float num = S_SCALE * (t * MARGIN_COS
                           - sqrtf(fmaxf(1.0f - t * t, 0.0f)) * MARGIN_SIN);
    float excl = g_excl[i] - __expf(S_SCALE * t);   // subtract target term
    float den = expf(num) + excl;
    float s = num - logf(den);
#pragma unroll
    for (int o = 16; o; o >>= 1) s += __shfl_xor_sync(0xFFFFFFFFu, s, o);
    if ((tid & 31) == 0) red[tid >> 5] = s;
    __syncthreads();
    if (tid < 16) {
        float v = red[tid];
#pragma unroll
        for (int o = 8; o; o >>= 1) v += __shfl_xor_sync(0xFFFFu, v, o);
        if (tid == 0) atomicAdd(&g_sum, v);
    }
}

__global__ void write_out_kernel(float* __restrict__ out) {
    out[0] = -g_sum / (float)N_ROWS;
}

// ---------------- launch ----------------
extern "C" void kernel_launch(void* const* d_in, const int* in_sizes, int n_in,
                              void* d_out, int out_size) {
    const float* x      = (const float*)d_in[0];
    const float* W      = (const float*)d_in[1];
    const int*   target = (const int*)d_in[2];
    float*       out    = (float*)d_out;

    cudaFuncSetAttribute(arc_gemm_kernel,
                         cudaFuncAttributeMaxDynamicSharedMemorySize, SMEM_TOTAL);

    conv_w_kernel<<<(int)(((size_t)NCLS * DIM) / 2048), 256>>>(W);
    prep_x_kernel<<<N_ROWS / 8, 256>>>(x, W, target);
    arc_gemm_kernel<<<dim3(MTILES, NTILES), 256, SMEM_TOTAL>>>();
    finalize_part_kernel<<<N_ROWS / 512, 512>>>();
    write_out_kernel<<<1, 1>>>(out);
}

// round 16
// speedup vs baseline: 2.3428x; 1.0136x over previous
#include <cuda_runtime.h>
#include <cuda_bf16.h>
#include <cstdint>
#include <cstddef>

#define DEV_INLINE __device__ __forceinline__

// ---------------- problem constants (fixed shapes) ----------------
constexpr int N_ROWS = 4096;
constexpr int DIM    = 512;
constexpr int NCLS   = 50000;
constexpr float S_SCALE    = 30.0f;
constexpr float EXP2C      = 43.280851226668905f;   // 30 * log2(e)
constexpr float MARGIN_COS = 0.9210609940028851f;   // cos(0.4)
constexpr float MARGIN_SIN = 0.3894183423086505f;   // sin(0.4)

// ---------------- GEMM tiling ----------------
constexpr int BM = 128;
constexpr int BN = 128;
constexpr int BK = 64;                 // 64 bf16 = 128B rows (SW128 atom)
constexpr int NKI = DIM / BK;          // 8 k-iterations
constexpr int NSTAGE = 3;
constexpr int MTILES = N_ROWS / BM;                  // 32
constexpr int NTILES = (NCLS + BN - 1) / BN;         // 391 (last masked)

constexpr uint32_t A_STAGE = BM * 128;               // 16384
constexpr uint32_t B_STAGE = BN * 128;               // 16384
constexpr uint32_t STAGE_BYTES = A_STAGE + B_STAGE;  // 32768
constexpr uint32_t SMEM_MBAR = NSTAGE * STAGE_BYTES;         // 98304
constexpr uint32_t SMEM_TOTAL = SMEM_MBAR + NSTAGE * 16;     // 98352 (x2 CTA)

// merged prep kernel block split
constexpr int WCONV_BLOCKS = (int)(((size_t)NCLS * DIM) / 2048);  // 12500
constexpr int PREP_BLOCKS  = N_ROWS / 8;                          // 512

// mbar layout: full[s] at SMEM_MBAR + s*16, empty[s] at +8
#define FULL_MB(s)  (sb + SMEM_MBAR + (s) * 16)
#define EMPTY_MB(s) (sb + SMEM_MBAR + (s) * 16 + 8)

// ---------------- device scratch (allocation-free rule) ----------------
__device__ __nv_bfloat16 g_xbf[(size_t)N_ROWS * DIM];   // normalized x, bf16
__device__ __nv_bfloat16 g_wbf[(size_t)NCLS * DIM];     // W, bf16 (51MB, mostly L2)
__device__ float g_excl[N_ROWS];    // FULL row exp-sum; target term subtracted in finalize
__device__ float g_tgt[N_ROWS];     // clamped fp32 target cosine (computed in prep)

// ---------------- helpers ----------------
DEV_INLINE uint32_t smem_u32(const void* p) { return (uint32_t)__cvta_generic_to_shared(p); }
DEV_INLINE uint32_t swz(uint32_t o) { return o ^ ((o >> 3) & 0x70); }

DEV_INLINE void cp16(uint32_t dst, const void* src) {
    asm volatile("cp.async.cg.shared.global [%0], [%1], 16;" :: "r"(dst), "l"(src));
}

DEV_INLINE void cp_arrive(uint32_t mbar) {
    asm volatile("cp.async.mbarrier.arrive.noinc.shared.b64 [%0];"
                 :: "r"(mbar) : "memory");
}

DEV_INLINE void mbar_arrive(uint32_t mbar) {
    asm volatile("mbarrier.arrive.shared.b64 _, [%0];" :: "r"(mbar) : "memory");
}

DEV_INLINE void mbar_wait(uint32_t mbar, uint32_t parity) {
    asm volatile(
        "{\n\t.reg .pred P1;\n\t"
        "WL_%=:\n\t"
        "mbarrier.try_wait.parity.acquire.cta.shared::cta.b64 P1, [%0], %1, 0x989680;\n\t"
        "@P1 bra.uni WD_%=;\n\t"
        "bra.uni WL_%=;\n\t"
        "WD_%=:\n\t}"
        :: "r"(mbar), "r"(parity) : "memory");
}

DEV_INLINE void ldm_x4(uint32_t& r0, uint32_t& r1, uint32_t& r2, uint32_t& r3,
                       uint32_t addr) {
    asm volatile("ldmatrix.sync.aligned.m8n8.x4.shared.b16 {%0,%1,%2,%3}, [%4];"
                 : "=r"(r0), "=r"(r1), "=r"(r2), "=r"(r3) : "r"(addr));
}

DEV_INLINE void mma_bf16(float* d, const uint32_t* a, uint32_t b0, uint32_t b1) {
    asm volatile(
        "mma.sync.aligned.m16n8k16.row.col.f32.bf16.bf16.f32 "
        "{%0,%1,%2,%3}, {%4,%5,%6,%7}, {%8,%9}, {%0,%1,%2,%3};"
        : "+f"(d[0]), "+f"(d[1]), "+f"(d[2]), "+f"(d[3])
        : "r"(a[0]), "r"(a[1]), "r"(a[2]), "r"(a[3]), "r"(b0), "r"(b1));
}

// ---------------- kernel 1: merged prep ----------------
// blocks [0, WCONV_BLOCKS): W fp32 -> bf16 (8 floats/thread, 16B store)
// blocks [WCONV_BLOCKS, +PREP_BLOCKS): x normalize -> bf16, fp32 target dot,
//                                      zero g_excl (one warp per row)
__global__ void prep_kernel(const float* __restrict__ W,
                            const float* __restrict__ x,
                            const int* __restrict__ target) {
    if (blockIdx.x < WCONV_BLOCKS) {
        size_t i = ((size_t)blockIdx.x * blockDim.x + threadIdx.x) * 8;
        float4 a = *reinterpret_cast<const float4*>(W + i);
        float4 b = *reinterpret_cast<const float4*>(W + i + 4);
        __nv_bfloat162 p0 = __floats2bfloat162_rn(a.x, a.y);
        __nv_bfloat162 p1 = __floats2bfloat162_rn(a.z, a.w);
        __nv_bfloat162 p2 = __floats2bfloat162_rn(b.x, b.y);
        __nv_bfloat162 p3 = __floats2bfloat162_rn(b.z, b.w);
        uint4 o;
        o.x = *reinterpret_cast<uint32_t*>(&p0);
        o.y = *reinterpret_cast<uint32_t*>(&p1);
        o.z = *reinterpret_cast<uint32_t*>(&p2);
        o.w = *reinterpret_cast<uint32_t*>(&p3);
        *reinterpret_cast<uint4*>(g_wbf + i) = o;
        return;
    }

    int row = (blockIdx.x - WCONV_BLOCKS) * 8 + (threadIdx.x >> 5);
    int lid = threadIdx.x & 31;
    const float4* xr = reinterpret_cast<const float4*>(x + (size_t)row * DIM);
    int tg = __ldg(target + row);
    const float4* wr = reinterpret_cast<const float4*>(W + (size_t)tg * DIM);

    float4 xv[4];
    float ss = 0.0f, dp = 0.0f;
#pragma unroll
    for (int j = 0; j < 4; j++) {
        float4 v = xr[lid + j * 32];
        float4 w = wr[lid + j * 32];
        xv[j] = v;
        ss += v.x * v.x + v.y * v.y + v.z * v.z + v.w * v.w;
        dp += v.x * w.x + v.y * w.y + v.z * w.z + v.w * w.w;
    }
#pragma unroll
    for (int o = 16; o; o >>= 1) {
        ss += __shfl_xor_sync(0xFFFFFFFFu, ss, o);
        dp += __shfl_xor_sync(0xFFFFFFFFu, dp, o);
    }
    float rn = rsqrtf(ss);
    __nv_bfloat16* outr = g_xbf + (size_t)row * DIM;
#pragma unroll
    for (int j = 0; j < 4; j++) {
        float4 v = xv[j];
        __nv_bfloat162 p0 = __floats2bfloat162_rn(v.x * rn, v.y * rn);
        __nv_bfloat162 p1 = __floats2bfloat162_rn(v.z * rn, v.w * rn);
        uint32_t u0 = *reinterpret_cast<uint32_t*>(&p0);
        uint32_t u1 = *reinterpret_cast<uint32_t*>(&p1);
        *reinterpret_cast<uint2*>(outr + (lid + j * 32) * 4) = make_uint2(u0, u1);
    }
    if (lid == 0) {
        float t = dp * rn;
        g_tgt[row]  = fminf(fmaxf(t, -1.0f + 1e-7f), 1.0f - 1e-7f);
        g_excl[row] = 0.0f;   // re-zero on every graph replay
    }
}

// ---------------- kernel 2: HMMA GEMM + branch-free exp-sum epilogue ----------
// BM=128 x BN=128, 8 warps 2x4, 64x32 warp tiles, 2 CTAs/SM, 3-stage mbarrier
// pipeline (no mainloop __syncthreads). Epilogue sums exp2(C*v) over ALL classes;
// the target term is subtracted later in finalize (no per-element branching).
__global__ void __launch_bounds__(256, 2)
arc_gemm_kernel() {
    extern __shared__ char smem[];
    const uint32_t sb = smem_u32(smem);

    const int tid = threadIdx.x;
    const int lid = tid & 31;
    const int wid = tid >> 5;
    const int wm  = wid & 1;          // 0..1  (m, 64 rows each)
    const int wn  = wid >> 1;         // 0..3  (n, 32 cols each)
    const int rbase = blockIdx.x * BM;
    const int cbase = blockIdx.y * BN;

    if (tid == 0) {
#pragma unroll
        for (int s = 0; s < NSTAGE; s++) {
            asm volatile("mbarrier.init.shared.b64 [%0], 256;" :: "r"(FULL_MB(s))  : "memory");
            asm volatile("mbarrier.init.shared.b64 [%0], 256;" :: "r"(EMPTY_MB(s)) : "memory");
        }
    }
    __syncthreads();   // mbarrier init visible before any arrive/wait

    // ---- cp.async source pointers & swizzled dst offsets, hoisted ----
    const int c_row = tid >> 3;          // rows advance by 32 per i
    const int c_kb  = tid & 7;
    const __nv_bfloat16* xp[4];
    const __nv_bfloat16* wp[4];
    uint32_t dstoff[4];
#pragma unroll
    for (int i = 0; i < 4; i++) {
        int row = c_row + i * 32;
        xp[i] = g_xbf + (size_t)(rbase + row) * DIM + c_kb * 8;
        int c = cbase + row; c = (c < NCLS) ? c : (NCLS - 1);  // clamp hoisted
        wp[i] = g_wbf + (size_t)c * DIM + c_kb * 8;
        dstoff[i] = swz(row * 128 + c_kb * 16);
    }

    // ---- LDSM address decomposition: addr = base + rowoff + xk[kk] ----
    const uint32_t a_row  = wm * 64 + (lid & 15);
    const uint32_t a_koff = (lid >> 4) * 16;
    const uint32_t b_row  = wn * 32 + (lid & 7) + ((lid >> 4) & 1) * 8;
    const uint32_t b_koff = ((lid >> 3) & 1) * 16;
    const uint32_t maskA  = (a_row & 7) << 4;
    const uint32_t maskB  = (b_row & 7) << 4;
    uint32_t offA[4], offB[2], xka[4], xkb[4];
#pragma unroll
    for (int mt = 0; mt < 4; mt++) offA[mt] = (a_row + mt * 16) * 128;
#pragma unroll
    for (int np = 0; np < 2; np++) offB[np] = (b_row + np * 16) * 128;
#pragma unroll
    for (int kk = 0; kk < 4; kk++) {
        xka[kk] = (kk * 32 + a_koff) ^ maskA;
        xkb[kk] = (kk * 32 + b_koff) ^ maskB;
    }

    float acc[4][4][4];
#pragma unroll
    for (int mt = 0; mt < 4; mt++)
#pragma unroll
        for (int nt = 0; nt < 4; nt++)
#pragma unroll
            for (int j = 0; j < 4; j++) acc[mt][nt][j] = 0.0f;

    // ---- prologue: fill stages 0 and 1 (fresh, no empty wait) ----
#pragma unroll
    for (int pk = 0; pk < 2; pk++) {
        const int k0 = pk * BK;
        const uint32_t sa  = sb + pk * STAGE_BYTES;
        const uint32_t sbb = sa + A_STAGE;
#pragma unroll
        for (int i = 0; i < 4; i++) cp16(sa + dstoff[i], xp[i] + k0);
#pragma unroll
        for (int i = 0; i < 4; i++) cp16(sbb + dstoff[i], wp[i] + k0);
        cp_arrive(FULL_MB(pk));
    }

    uint32_t afr[4][4];
    uint32_t bfr[4][2];

    // ---- mainloop: fully unrolled; stage s=k%3, full parity (k/3)&1.
#pragma unroll
    for (int k = 0; k < NKI; k++) {
        const int s = k % 3;
        const uint32_t abase = sb + s * STAGE_BYTES;
        const uint32_t bbase = abase + A_STAGE;

        mbar_wait(FULL_MB(s), (k / 3) & 1);

        // kk=0 fragment loads first: crossbar starts immediately
        {
            const uint32_t ax = abase + xka[0];
            const uint32_t bx = bbase + xkb[0];
#pragma unroll
            for (int mt = 0; mt < 4; mt++)
                ldm_x4(afr[mt][0], afr[mt][1], afr[mt][2], afr[mt][3], ax + offA[mt]);
#pragma unroll
            for (int np = 0; np < 2; np++) {
                uint32_t r0, r1, r2, r3;
                ldm_x4(r0, r1, r2, r3, bx + offB[np]);
                bfr[np * 2][0] = r0;     bfr[np * 2][1] = r1;
                bfr[np * 2 + 1][0] = r2; bfr[np * 2 + 1][1] = r3;
            }
        }

        // produce stage k+2
        if (k + 2 < NKI) {
            const int s2 = (k + 2) % 3;
            const int fi = (k + 2) / 3;          // 0 => fresh (stage 2 only)
            if (k + 2 > 2) mbar_wait(EMPTY_MB(s2), (fi - 1) & 1);
            const int k0 = (k + 2) * BK;
            const uint32_t sa  = sb + s2 * STAGE_BYTES;
            const uint32_t sbb = sa + A_STAGE;
#pragma unroll
            for (int i = 0; i < 4; i++) cp16(sa + dstoff[i], xp[i] + k0);
#pragma unroll
            for (int i = 0; i < 4; i++) cp16(sbb + dstoff[i], wp[i] + k0);
            cp_arrive(FULL_MB(s2));
        }

        // kk loop: MMA(kk), then LDSM(kk+1)
#pragma unroll
        for (int kk = 0; kk < 4; kk++) {
#pragma unroll
            for (int mt = 0; mt < 4; mt++)
#pragma unroll
                for (int nt = 0; nt < 4; nt++)
                    mma_bf16(acc[mt][nt], afr[mt], bfr[nt][0], bfr[nt][1]);
            if (kk < 3) {
                const uint32_t ax = abase + xka[kk + 1];
                const uint32_t bx = bbase + xkb[kk + 1];
#pragma unroll
                for (int mt = 0; mt < 4; mt++)
                    ldm_x4(afr[mt][0], afr[mt][1], afr[mt][2], afr[mt][3],
                           ax + offA[mt]);
#pragma unroll
                for (int np = 0; np < 2; np++) {
                    uint32_t r0, r1, r2, r3;
                    ldm_x4(r0, r1, r2, r3, bx + offB[np]);
                    bfr[np * 2][0] = r0;     bfr[np * 2][1] = r1;
                    bfr[np * 2 + 1][0] = r2; bfr[np * 2 + 1][1] = r3;
                }
            }
        }

        // release stage for refill (only while fills remain)
        if (k + 3 < NKI) mbar_arrive(EMPTY_MB(s));
    }

    // ---- branch-free epilogue: full exp2-sum, one RED per quad, no syncs ----
    // c-frag: d0=(r,c0) d1=(r,c0+1) d2=(r+8,c0) d3=(r+8,c0+1); r=lid>>2, c0=2*(lid&3)
    if (cbase + BN <= NCLS) {
        // fast path: all 128 columns valid (390 of 391 tiles)
#pragma unroll
        for (int mt = 0; mt < 4; mt++) {
#pragma unroll
            for (int h = 0; h < 2; h++) {
                int grow = rbase + wm * 64 + mt * 16 + (lid >> 2) + h * 8;
                float s = 0.0f;
#pragma unroll
                for (int nt = 0; nt < 4; nt++) {
                    s += exp2f(EXP2C * acc[mt][nt][h * 2]);
                    s += exp2f(EXP2C * acc[mt][nt][h * 2 + 1]);
                }
                s += __shfl_xor_sync(0xFFFFFFFFu, s, 1);
                s += __shfl_xor_sync(0xFFFFFFFFu, s, 2);
                if ((lid & 3) == 0) atomicAdd(&g_excl[grow], s);
            }
        }
    } else {
        // tail tile: mask c >= NCLS (clamp-loaded duplicates)
#pragma unroll
        for (int mt = 0; mt < 4; mt++) {
#pragma unroll
            for (int h = 0; h < 2; h++) {
                int grow = rbase + wm * 64 + mt * 16 + (lid >> 2) + h * 8;
                float s = 0.0f;
#pragma unroll
                for (int nt = 0; nt < 4; nt++) {
#pragma unroll
                    for (int j = 0; j < 2; j++) {
                        int c = cbase + wn * 32 + nt * 8 + 2 * (lid & 3) + j;
                        if (c < NCLS) s += exp2f(EXP2C * acc[mt][nt][h * 2 + j]);
                    }
                }
                s += __shfl_xor_sync(0xFFFFFFFFu, s, 1);
                s += __shfl_xor_sync(0xFFFFFFFFu, s, 2);
                if ((lid & 3) == 0) atomicAdd(&g_excl[grow], s);
            }
        }
    }
}

// ---------------- kernel 3: finalize — single block, writes output ----------
__global__ void finalize_kernel(float* __restrict__ out) {
    __shared__ float red[32];
    int tid = threadIdx.x;   // 1024 threads
    float s = 0.0f;
#pragma unroll
    for (int j = 0; j < N_ROWS / 1024; j++) {
        int i = tid + j * 1024;
        float t = g_tgt[i];   // already clamped fp32 cosine
        float num = S_SCALE * (t * MARGIN_COS
                               - sqrtf(fmaxf(1.0f - t * t, 0.0f)) * MARGIN_SIN);
        float excl = g_excl[i] - exp2f(EXP2C * t);   // subtract target term
        float den = expf(num) + excl;
        s += num - logf(den);
    }
#pragma unroll
    for (int o = 16; o; o >>= 1) s += __shfl_xor_sync(0xFFFFFFFFu, s, o);
    if ((tid & 31) == 0) red[tid >> 5] = s;
    __syncthreads();
    if (tid < 32) {
        float v = red[tid];
#pragma unroll
        for (int o = 16; o; o >>= 1) v += __shfl_xor_sync(0xFFFFFFFFu, v, o);
        if (tid == 0) out[0] = -v / (float)N_ROWS;
    }
}

// ---------------- launch ----------------
extern "C" void kernel_launch(void* const* d_in, const int* in_sizes, int n_in,
                              void* d_out, int out_size) {
    const float* x      = (const float*)d_in[0];
    const float* W      = (const float*)d_in[1];
    const int*   target = (const int*)d_in[2];
    float*       out    = (float*)d_out;

    cudaFuncSetAttribute(arc_gemm_kernel,
                         cudaFuncAttributeMaxDynamicSharedMemorySize, SMEM_TOTAL);

    prep_kernel<<<WCONV_BLOCKS + PREP_BLOCKS, 256>>>(W, x, target);
    arc_gemm_kernel<<<dim3(MTILES, NTILES), 256, SMEM_TOTAL>>>();
    finalize_kernel<<<1, 1024>>>(out);
}